// round 15
// baseline (speedup 1.0000x reference)
#include <cuda_runtime.h>
#include <math.h>

// Problem constants (fixed shapes)
#define Bc  256
#define Tc  512
#define Ec  200
#define Hc  100
#define G3  300   // 3*H
#define NCc 5

// Scratch (device globals — no allocation allowed)
__device__ float g_rnorm[Bc * Tc];               // 0.5 MB per-row normalization scale
__device__ float g_xp[(size_t)Bc * Tc * G3];     // 157.3 MB  xp = A @ W_ih^T + b_ih

// ---------------------------------------------------------------------------
// Kernel 1: per-row embedding norm scale.  One warp per (b,t) row.
// ---------------------------------------------------------------------------
__global__ void row_norm_kernel(const int* __restrict__ txt,
                                const float* __restrict__ emb) {
    int row  = blockIdx.x * 8 + (threadIdx.x >> 5);
    int lane = threadIdx.x & 31;
    int tok  = txt[row];
    const float* src = emb + (size_t)tok * Ec;

    float ss = 0.f;
#pragma unroll
    for (int it = 0; it < 7; it++) {
        int k = lane + it * 32;
        float v = (k < Ec) ? src[k] : 0.f;
        ss += v * v;
    }
#pragma unroll
    for (int o = 16; o; o >>= 1) ss += __shfl_xor_sync(0xffffffffu, ss, o);

    if (lane == 0) {
        float n = sqrtf(ss);
        g_rnorm[row] = (n > 1.0f) ? 1.0f / (n + 1e-7f) : 1.0f;
    }
}

// ---------------------------------------------------------------------------
// Kernel 2: xp = (emb[txt] * rnorm) @ W_ih^T + b_ih.  M=131072, K=200, N=300.
// Tiles: BM=128, BN=64, BK=8.  256 threads, 8x4 per-thread tile.
// Grid: x = n (5 blocks), y = m (1024 blocks) so the 5 n-blocks sharing one
// A row-tile are adjacent in schedule order -> A read from DRAM once via L2.
// A rows are gathered from emb and scaled in-flight (token/scale hoisted).
// ---------------------------------------------------------------------------
__global__ void gemm_xp_kernel(const int* __restrict__ txt,
                               const float* __restrict__ emb,
                               const float* __restrict__ W,
                               const float* __restrict__ bias) {
    __shared__ float As[8][128];
    __shared__ float Ws[8][64];

    const int tid = threadIdx.x;
    const int bm  = blockIdx.y * 128;   // m tile
    const int bn  = blockIdx.x * 64;    // n tile
    const int tx  = tid & 15;   // n direction
    const int ty  = tid >> 4;   // m direction

    float acc[8][4];
#pragma unroll
    for (int i = 0; i < 8; i++)
#pragma unroll
        for (int jj = 0; jj < 4; jj++) acc[i][jj] = 0.f;

    const int ar = tid >> 1;            // A row within tile (0..127)
    const int ak = (tid & 1) << 2;      // A k offset (0 or 4)

    // Loop-invariant per thread: token row pointer + normalization scale
    const int   tok   = txt[bm + ar];
    const float ascal = g_rnorm[bm + ar];
    const float* arow = emb + (size_t)tok * Ec;

    const int wr = (tid < 128) ? (tid >> 1) : 0;
    const int wk = (tid < 128) ? ((tid & 1) << 2) : 0;

    for (int k0 = 0; k0 < Ec; k0 += 8) {
        float4 av = *(const float4*)(arow + k0 + ak);
        av.x *= ascal; av.y *= ascal; av.z *= ascal; av.w *= ascal;

        float4 wv = make_float4(0.f, 0.f, 0.f, 0.f);
        if (tid < 128) {
            int n = bn + wr;
            if (n < G3) wv = *(const float4*)(W + (size_t)n * Ec + k0 + wk);
        }
        __syncthreads();   // protect previous iteration's reads
        As[ak + 0][ar] = av.x; As[ak + 1][ar] = av.y;
        As[ak + 2][ar] = av.z; As[ak + 3][ar] = av.w;
        if (tid < 128) {
            Ws[wk + 0][wr] = wv.x; Ws[wk + 1][wr] = wv.y;
            Ws[wk + 2][wr] = wv.z; Ws[wk + 3][wr] = wv.w;
        }
        __syncthreads();

#pragma unroll
        for (int kk = 0; kk < 8; kk++) {
            float4 a0 = *(const float4*)&As[kk][ty * 8];
            float4 a1 = *(const float4*)&As[kk][ty * 8 + 4];
            float4 w0 = *(const float4*)&Ws[kk][tx * 4];
            float a[8] = {a0.x, a0.y, a0.z, a0.w, a1.x, a1.y, a1.z, a1.w};
            float w[4] = {w0.x, w0.y, w0.z, w0.w};
#pragma unroll
            for (int i = 0; i < 8; i++)
#pragma unroll
                for (int jj = 0; jj < 4; jj++) acc[i][jj] += a[i] * w[jj];
        }
    }

#pragma unroll
    for (int i = 0; i < 8; i++) {
        int m = bm + ty * 8 + i;
#pragma unroll
        for (int jj = 0; jj < 4; jj++) {
            int n = bn + tx * 4 + jj;
            if (n < G3) g_xp[(size_t)m * G3 + n] = acc[i][jj] + bias[n];
        }
    }
}

// ---------------------------------------------------------------------------
// Kernel 3: fused dual scan.  128 blocks x 320 threads; each block owns 2
// batch elements and iterates t = 0..511.  All weights in shared memory.
// Per step: A) hp = h@W_hh^T (+xp prefetch)  B) GRU gate math, h update
//           C) ti = h@W_ti^T, sts = state@W_ts^T, attention & gate scalars
//           D) state update.   3 __syncthreads per step.
// ---------------------------------------------------------------------------
#define SCAN_THREADS 320
#define SCAN_SMEM_FLOATS (30000 + 10000 + 10000 + 100 + 100 + 300 + 100 + 100 \
                          + 200 + 200 + 600 + 600 + 8)

__global__ void scan_kernel(const float* __restrict__ W_hh,
                            const float* __restrict__ b_hh,
                            const float* __restrict__ W_lgr,
                            const float* __restrict__ b_lgr,
                            const float* __restrict__ W_ts,
                            const float* __restrict__ b_ts,
                            const float* __restrict__ W_ti,
                            const float* __restrict__ b_ti,
                            const float* __restrict__ W_out,
                            const float* __restrict__ b_out,
                            const int* __restrict__ lens,
                            float* __restrict__ out) {
    extern __shared__ float sm[];
    float* sWhh   = sm;                  // 30000  [300][100]
    float* sWti   = sWhh + 30000;        // 10000  [100][100]
    float* sWts   = sWti + 10000;        // 10000  [100][100]
    float* sWlgr  = sWts + 10000;        // 100
    float* sWls   = sWlgr + 100;         // 100
    float* sbhh   = sWls + 100;          // 300
    float* sbti   = sbhh + 300;          // 100
    float* sbts   = sbti + 100;          // 100
    float* sh     = sbts + 100;          // 200  h for 2 batches
    float* sstate = sh + 200;            // 200
    float* shp    = sstate + 200;        // 600
    float* sxq    = shp + 600;           // 600
    float* ssc    = sxq + 600;           // 8: z[2], gate[2]

    const int tid = threadIdx.x;
    const int gb0 = blockIdx.x * 2;

    for (int i = tid; i < 30000; i += SCAN_THREADS) sWhh[i] = W_hh[i];
    for (int i = tid; i < 10000; i += SCAN_THREADS) { sWti[i] = W_ti[i]; sWts[i] = W_ts[i]; }
    for (int i = tid; i < 300;   i += SCAN_THREADS) sbhh[i] = b_hh[i];
    if (tid < 100) {
        sWlgr[tid] = W_lgr[tid];
        sWls[tid]  = W_lgr[100 + tid];
        sbti[tid]  = b_ti[tid];
        sbts[tid]  = b_ts[tid];
    }
    for (int i = tid; i < 200; i += SCAN_THREADS) { sh[i] = 0.f; sstate[i] = 0.f; }
    const float blgr = b_lgr[0];
    const int len0 = lens[gb0];
    const int len1 = lens[gb0 + 1];
    __syncthreads();

    float acc_ti = 0.f, acc_sts = 0.f;

    for (int t = 0; t < Tc; t++) {
        // ---- Stage A: hp matvec + xp prefetch ------------------------------
        if (tid < 300) {
            float xv0 = g_xp[((size_t)gb0 * Tc + t) * G3 + tid];
            float xv1 = g_xp[((size_t)(gb0 + 1) * Tc + t) * G3 + tid];
            float a0 = sbhh[tid], a1 = sbhh[tid];
            const float4* wrow = (const float4*)(sWhh + tid * Hc);
            const float4* h0p  = (const float4*)(sh);
            const float4* h1p  = (const float4*)(sh + Hc);
#pragma unroll
            for (int k = 0; k < 25; k++) {
                float4 w  = wrow[k];
                float4 x0 = h0p[k];
                float4 x1 = h1p[k];
                a0 += w.x * x0.x + w.y * x0.y + w.z * x0.z + w.w * x0.w;
                a1 += w.x * x1.x + w.y * x1.y + w.z * x1.z + w.w * x1.w;
            }
            shp[tid] = a0; shp[300 + tid] = a1;
            sxq[tid] = xv0; sxq[300 + tid] = xv1;
        }
        __syncthreads();

        // ---- Stage B: GRU gates, h update ----------------------------------
        if (tid < 200) {
            int b = tid & 1, i = tid >> 1;
            const float* xq = sxq + b * 300;
            const float* hp = shp + b * 300;
            float r  = 1.f / (1.f + expf(-(xq[i] + hp[i])));
            float zg = 1.f / (1.f + expf(-(xq[100 + i] + hp[100 + i])));
            float ng = tanhf(xq[200 + i] + r * hp[200 + i]);
            float hold = sh[b * Hc + i];
            sh[b * Hc + i] = (1.f - zg) * ng + zg * hold;
        }
        __syncthreads();

        // ---- Stage C: ti/sts matvecs + attention/gate scalars --------------
        if (tid < 200) {
            int b = tid & 1, i = tid >> 1;
            float ti = sbti[i], ss = 0.f;
            const float4* wti = (const float4*)(sWti + i * Hc);
            const float4* wts = (const float4*)(sWts + i * Hc);
            const float4* hb  = (const float4*)(sh + b * Hc);
            const float4* st  = (const float4*)(sstate + b * Hc);
#pragma unroll
            for (int k = 0; k < 25; k++) {
                float4 w1 = wti[k], hv = hb[k];
                ti += w1.x * hv.x + w1.y * hv.y + w1.z * hv.z + w1.w * hv.w;
                float4 w2 = wts[k], sv = st[k];
                ss += w2.x * sv.x + w2.y * sv.y + w2.z * sv.z + w2.w * sv.w;
            }
            acc_ti = ti; acc_sts = ss;
        } else if (tid >= 256) {
            int b = (tid >= 288) ? 1 : 0;
            int lane = tid & 31;
            const float* hb = sh + b * Hc;
            const float* st = sstate + b * Hc;
            float s1 = 0.f, s2 = 0.f, s3 = 0.f, s4 = 0.f;
#pragma unroll
            for (int it = 0; it < 3; it++) {
                int k = lane + it * 32;
                float hv = hb[k];
                s1 += hv; s2 += hv * hv; s3 += hv * sWlgr[k]; s4 += st[k] * sWls[k];
            }
            if (lane < 4) {
                int k = lane + 96;
                float hv = hb[k];
                s1 += hv; s2 += hv * hv; s3 += hv * sWlgr[k]; s4 += st[k] * sWls[k];
            }
#pragma unroll
            for (int o = 16; o; o >>= 1) {
                s1 += __shfl_xor_sync(0xffffffffu, s1, o);
                s2 += __shfl_xor_sync(0xffffffffu, s2, o);
                s3 += __shfl_xor_sync(0xffffffffu, s3, o);
                s4 += __shfl_xor_sync(0xffffffffu, s4, o);
            }
            if (lane == 0) {
                float norm  = sqrtf(s2);
                float denom = fmaxf(norm, 1e-12f);
                float att   = (s1 / denom) * 0.001f;     // qn = 0.1, /H = /100
                int   len   = b ? len1 : len0;
                float z     = (t < len) ? fmaxf(att, 0.f) : 0.f;
                float gate  = 1.f / (1.f + expf(-(s3 + s4 + blgr)));
                ssc[b]     = z;
                ssc[2 + b] = gate;
            }
        }
        __syncthreads();

        // ---- Stage D: state update -----------------------------------------
        if (tid < 200) {
            int b = tid & 1, i = tid >> 1;
            float z    = ssc[b];
            float gate = ssc[2 + b];
            float ns   = tanhf(acc_ti + gate * acc_sts + sbts[i]);
            float sold = sstate[b * Hc + i];
            sstate[b * Hc + i] = (1.f - z) * sold + z * ns;
        }
        // no sync needed: next reads of sstate happen after >=2 barriers
    }
    __syncthreads();

    // ---- Output head: out = state @ W_out^T + b_out ------------------------
    if (tid < 2 * NCc) {
        int b = tid / NCc, c = tid % NCc;
        float acc = b_out[c];
        const float* st = sstate + b * Hc;
        for (int k = 0; k < Hc; k++) acc += st[k] * W_out[c * Hc + k];
        out[(gb0 + b) * NCc + c] = acc;
    }
}

// ---------------------------------------------------------------------------
extern "C" void kernel_launch(void* const* d_in, const int* in_sizes, int n_in,
                              void* d_out, int out_size) {
    const int*   txt   = (const int*)d_in[0];
    const int*   lens  = (const int*)d_in[1];
    const float* emb   = (const float*)d_in[2];
    const float* W_ih  = (const float*)d_in[3];
    const float* W_hh  = (const float*)d_in[4];
    const float* b_ih  = (const float*)d_in[5];
    const float* b_hh  = (const float*)d_in[6];
    const float* W_lgr = (const float*)d_in[7];
    const float* b_lgr = (const float*)d_in[8];
    const float* W_ts  = (const float*)d_in[9];
    const float* b_ts  = (const float*)d_in[10];
    const float* W_ti  = (const float*)d_in[11];
    const float* b_ti  = (const float*)d_in[12];
    const float* W_out = (const float*)d_in[13];
    const float* b_out = (const float*)d_in[14];
    float*       out   = (float*)d_out;

    (void)in_sizes; (void)n_in; (void)out_size;

    // Kernel 1: per-row norm scales (one warp per row)
    row_norm_kernel<<<(Bc * Tc) / 8, 256>>>(txt, emb);

    // Kernel 2: xp GEMM.  grid.x = n (5), grid.y = m (1024) for A-tile L2 reuse
    dim3 g2(5, (Bc * Tc) / 128);
    gemm_xp_kernel<<<g2, 256>>>(txt, emb, W_ih, b_ih);

    // Kernel 3: fused scans
    static const size_t smem_bytes = SCAN_SMEM_FLOATS * sizeof(float);
    cudaFuncSetAttribute(scan_kernel,
                         cudaFuncAttributeMaxDynamicSharedMemorySize,
                         (int)smem_bytes);
    scan_kernel<<<Bc / 2, SCAN_THREADS, smem_bytes>>>(
        W_hh, b_hh, W_lgr, b_lgr, W_ts, b_ts, W_ti, b_ti, W_out, b_out,
        lens, out);
}

// round 16
// speedup vs baseline: 1.0259x; 1.0259x over previous
#include <cuda_runtime.h>
#include <math.h>
#include <stdint.h>

// Problem constants (fixed shapes)
#define Bc  256
#define Tc  512
#define Ec  200
#define Hc  100
#define G3  300   // 3*H
#define NCc 5

// Scratch (device globals — no allocation allowed)
__device__ float g_rnorm[Bc * Tc];               // 0.5 MB per-row normalization scale
__device__ float g_xp[(size_t)Bc * Tc * G3];     // 157.3 MB  xp = A @ W_ih^T + b_ih

// ---------------------------------------------------------------------------
// Kernel 1: per-row embedding norm scale.  One warp per (b,t) row.
// ---------------------------------------------------------------------------
__global__ void row_norm_kernel(const int* __restrict__ txt,
                                const float* __restrict__ emb) {
    int row  = blockIdx.x * 8 + (threadIdx.x >> 5);
    int lane = threadIdx.x & 31;
    int tok  = txt[row];
    const float* src = emb + (size_t)tok * Ec;

    float ss = 0.f;
#pragma unroll
    for (int it = 0; it < 7; it++) {
        int k = lane + it * 32;
        float v = (k < Ec) ? src[k] : 0.f;
        ss += v * v;
    }
#pragma unroll
    for (int o = 16; o; o >>= 1) ss += __shfl_xor_sync(0xffffffffu, ss, o);

    if (lane == 0) {
        float n = sqrtf(ss);
        g_rnorm[row] = (n > 1.0f) ? 1.0f / (n + 1e-7f) : 1.0f;
    }
}

// ---------------------------------------------------------------------------
// Kernel 2 (v2): xp = (emb[txt]*rnorm) @ W_ih^T + b_ih via 3xTF32 mma.sync.
// BM=128, BN=64, BK=8; 256 threads = 8 warps in 4(m) x 2(n) grid; each warp
// owns a 32x32 output tile = 2(m16) x 4(n8) mma tiles, 3 mma each (hi*hi,
// hi*lo, lo*hi) for fp32-accurate accumulation.  Smem rows padded to 136/72
// floats -> conflict-free fragment loads.
// ---------------------------------------------------------------------------
__device__ __forceinline__ uint32_t f32_to_tf32_bits(float v) {
    uint32_t r;
    asm("cvt.rna.tf32.f32 %0, %1;" : "=r"(r) : "f"(v));
    return r;
}

__device__ __forceinline__ void mma_tf32(float* d, const uint32_t* a,
                                         const uint32_t* b) {
    asm volatile(
        "mma.sync.aligned.m16n8k8.row.col.f32.tf32.tf32.f32 "
        "{%0,%1,%2,%3}, {%4,%5,%6,%7}, {%8,%9}, {%0,%1,%2,%3};\n"
        : "+f"(d[0]), "+f"(d[1]), "+f"(d[2]), "+f"(d[3])
        : "r"(a[0]), "r"(a[1]), "r"(a[2]), "r"(a[3]), "r"(b[0]), "r"(b[1]));
}

__global__ void gemm_xp_tf32_kernel(const int* __restrict__ txt,
                                    const float* __restrict__ emb,
                                    const float* __restrict__ W,
                                    const float* __restrict__ bias) {
    __shared__ float Ah[8][136], Al[8][136];   // A tile, tf32 hi/lo, [k][m]
    __shared__ float Bh[8][72],  Bl[8][72];    // B tile, tf32 hi/lo, [k][n]

    const int tid  = threadIdx.x;
    const int bm   = blockIdx.y * 128;
    const int bn   = blockIdx.x * 64;
    const int wid  = tid >> 5;
    const int lane = tid & 31;
    const int wm0  = (wid & 3) * 32;   // warp m offset within tile
    const int wn0  = (wid >> 2) * 32;  // warp n offset within tile
    const int g    = lane >> 2;        // 0..7
    const int tg   = lane & 3;         // 0..3

    float d[2][4][4];
#pragma unroll
    for (int mt = 0; mt < 2; mt++)
#pragma unroll
        for (int nt = 0; nt < 4; nt++)
#pragma unroll
            for (int r = 0; r < 4; r++) d[mt][nt][r] = 0.f;

    // A loader mapping (all 256 threads): row ar, k-offset ak
    const int ar = tid >> 1;
    const int ak = (tid & 1) << 2;
    const int   tok   = txt[bm + ar];
    const float ascal = g_rnorm[bm + ar];
    const float* arow = emb + (size_t)tok * Ec;

    // B loader mapping (threads 0..127): row wr (n), k-offset wk
    const int wr = tid >> 1;
    const int wk = (tid & 1) << 2;

    for (int k0 = 0; k0 < Ec; k0 += 8) {
        float4 av = *(const float4*)(arow + k0 + ak);
        av.x *= ascal; av.y *= ascal; av.z *= ascal; av.w *= ascal;

        float4 wv = make_float4(0.f, 0.f, 0.f, 0.f);
        if (tid < 128) {
            int n = bn + wr;
            if (n < G3) wv = *(const float4*)(W + (size_t)n * Ec + k0 + wk);
        }
        __syncthreads();   // protect previous iteration's fragment reads

        {
            float va[4] = {av.x, av.y, av.z, av.w};
#pragma unroll
            for (int j = 0; j < 4; j++) {
                uint32_t hb = f32_to_tf32_bits(va[j]);
                float hi = __uint_as_float(hb);
                float lo = va[j] - hi;
                Ah[ak + j][ar] = hi;
                Al[ak + j][ar] = __uint_as_float(f32_to_tf32_bits(lo));
            }
            if (tid < 128) {
                float vb[4] = {wv.x, wv.y, wv.z, wv.w};
#pragma unroll
                for (int j = 0; j < 4; j++) {
                    uint32_t hb = f32_to_tf32_bits(vb[j]);
                    float hi = __uint_as_float(hb);
                    float lo = vb[j] - hi;
                    Bh[wk + j][wr] = hi;
                    Bl[wk + j][wr] = __uint_as_float(f32_to_tf32_bits(lo));
                }
            }
        }
        __syncthreads();

        // Fragment loads (conflict-free: bank = (tg*8 + g + c) mod 32)
        uint32_t afh[2][4], afl[2][4], bfh[4][2], bfl[4][2];
#pragma unroll
        for (int mt = 0; mt < 2; mt++) {
            int m = wm0 + mt * 16 + g;
            afh[mt][0] = __float_as_uint(Ah[tg][m]);
            afh[mt][1] = __float_as_uint(Ah[tg][m + 8]);
            afh[mt][2] = __float_as_uint(Ah[tg + 4][m]);
            afh[mt][3] = __float_as_uint(Ah[tg + 4][m + 8]);
            afl[mt][0] = __float_as_uint(Al[tg][m]);
            afl[mt][1] = __float_as_uint(Al[tg][m + 8]);
            afl[mt][2] = __float_as_uint(Al[tg + 4][m]);
            afl[mt][3] = __float_as_uint(Al[tg + 4][m + 8]);
        }
#pragma unroll
        for (int nt = 0; nt < 4; nt++) {
            int n = wn0 + nt * 8 + g;
            bfh[nt][0] = __float_as_uint(Bh[tg][n]);
            bfh[nt][1] = __float_as_uint(Bh[tg + 4][n]);
            bfl[nt][0] = __float_as_uint(Bl[tg][n]);
            bfl[nt][1] = __float_as_uint(Bl[tg + 4][n]);
        }

#pragma unroll
        for (int mt = 0; mt < 2; mt++)
#pragma unroll
            for (int nt = 0; nt < 4; nt++) {
                mma_tf32(d[mt][nt], afl[mt], bfh[nt]);   // lo*hi
                mma_tf32(d[mt][nt], afh[mt], bfl[nt]);   // hi*lo
                mma_tf32(d[mt][nt], afh[mt], bfh[nt]);   // hi*hi
            }
    }

    // Epilogue: D[m][n] fragment c0=[g][2tg], c1=[g][2tg+1], c2=[g+8][..]
#pragma unroll
    for (int mt = 0; mt < 2; mt++) {
        int m = bm + wm0 + mt * 16 + g;
#pragma unroll
        for (int nt = 0; nt < 4; nt++) {
            int n = bn + wn0 + nt * 8 + tg * 2;
            if (n < G3) {   // n even -> n+1 <= 299 whenever n < 300
                float b0 = bias[n], b1 = bias[n + 1];
                g_xp[(size_t)m * G3 + n]           = d[mt][nt][0] + b0;
                g_xp[(size_t)m * G3 + n + 1]       = d[mt][nt][1] + b1;
                g_xp[(size_t)(m + 8) * G3 + n]     = d[mt][nt][2] + b0;
                g_xp[(size_t)(m + 8) * G3 + n + 1] = d[mt][nt][3] + b1;
            }
        }
    }
}

// ---------------------------------------------------------------------------
// Kernel 3: fused dual scan.  128 blocks x 320 threads; each block owns 2
// batch elements and iterates t = 0..511.  All weights in shared memory.
// ---------------------------------------------------------------------------
#define SCAN_THREADS 320
#define SCAN_SMEM_FLOATS (30000 + 10000 + 10000 + 100 + 100 + 300 + 100 + 100 \
                          + 200 + 200 + 600 + 600 + 8)

__global__ void scan_kernel(const float* __restrict__ W_hh,
                            const float* __restrict__ b_hh,
                            const float* __restrict__ W_lgr,
                            const float* __restrict__ b_lgr,
                            const float* __restrict__ W_ts,
                            const float* __restrict__ b_ts,
                            const float* __restrict__ W_ti,
                            const float* __restrict__ b_ti,
                            const float* __restrict__ W_out,
                            const float* __restrict__ b_out,
                            const int* __restrict__ lens,
                            float* __restrict__ out) {
    extern __shared__ float sm[];
    float* sWhh   = sm;                  // 30000  [300][100]
    float* sWti   = sWhh + 30000;        // 10000  [100][100]
    float* sWts   = sWti + 10000;        // 10000  [100][100]
    float* sWlgr  = sWts + 10000;        // 100
    float* sWls   = sWlgr + 100;         // 100
    float* sbhh   = sWls + 100;          // 300
    float* sbti   = sbhh + 300;          // 100
    float* sbts   = sbti + 100;          // 100
    float* sh     = sbts + 100;          // 200  h for 2 batches
    float* sstate = sh + 200;            // 200
    float* shp    = sstate + 200;        // 600
    float* sxq    = shp + 600;           // 600
    float* ssc    = sxq + 600;           // 8: z[2], gate[2]

    const int tid = threadIdx.x;
    const int gb0 = blockIdx.x * 2;

    for (int i = tid; i < 30000; i += SCAN_THREADS) sWhh[i] = W_hh[i];
    for (int i = tid; i < 10000; i += SCAN_THREADS) { sWti[i] = W_ti[i]; sWts[i] = W_ts[i]; }
    for (int i = tid; i < 300;   i += SCAN_THREADS) sbhh[i] = b_hh[i];
    if (tid < 100) {
        sWlgr[tid] = W_lgr[tid];
        sWls[tid]  = W_lgr[100 + tid];
        sbti[tid]  = b_ti[tid];
        sbts[tid]  = b_ts[tid];
    }
    for (int i = tid; i < 200; i += SCAN_THREADS) { sh[i] = 0.f; sstate[i] = 0.f; }
    const float blgr = b_lgr[0];
    const int len0 = lens[gb0];
    const int len1 = lens[gb0 + 1];
    __syncthreads();

    float acc_ti = 0.f, acc_sts = 0.f;

    for (int t = 0; t < Tc; t++) {
        // ---- Stage A: hp matvec + xp prefetch ------------------------------
        if (tid < 300) {
            float xv0 = g_xp[((size_t)gb0 * Tc + t) * G3 + tid];
            float xv1 = g_xp[((size_t)(gb0 + 1) * Tc + t) * G3 + tid];
            float a0 = sbhh[tid], a1 = sbhh[tid];
            const float4* wrow = (const float4*)(sWhh + tid * Hc);
            const float4* h0p  = (const float4*)(sh);
            const float4* h1p  = (const float4*)(sh + Hc);
#pragma unroll
            for (int k = 0; k < 25; k++) {
                float4 w  = wrow[k];
                float4 x0 = h0p[k];
                float4 x1 = h1p[k];
                a0 += w.x * x0.x + w.y * x0.y + w.z * x0.z + w.w * x0.w;
                a1 += w.x * x1.x + w.y * x1.y + w.z * x1.z + w.w * x1.w;
            }
            shp[tid] = a0; shp[300 + tid] = a1;
            sxq[tid] = xv0; sxq[300 + tid] = xv1;
        }
        __syncthreads();

        // ---- Stage B: GRU gates, h update ----------------------------------
        if (tid < 200) {
            int b = tid & 1, i = tid >> 1;
            const float* xq = sxq + b * 300;
            const float* hp = shp + b * 300;
            float r  = 1.f / (1.f + expf(-(xq[i] + hp[i])));
            float zg = 1.f / (1.f + expf(-(xq[100 + i] + hp[100 + i])));
            float ng = tanhf(xq[200 + i] + r * hp[200 + i]);
            float hold = sh[b * Hc + i];
            sh[b * Hc + i] = (1.f - zg) * ng + zg * hold;
        }
        __syncthreads();

        // ---- Stage C: ti/sts matvecs + attention/gate scalars --------------
        if (tid < 200) {
            int b = tid & 1, i = tid >> 1;
            float ti = sbti[i], ss = 0.f;
            const float4* wti = (const float4*)(sWti + i * Hc);
            const float4* wts = (const float4*)(sWts + i * Hc);
            const float4* hb  = (const float4*)(sh + b * Hc);
            const float4* st  = (const float4*)(sstate + b * Hc);
#pragma unroll
            for (int k = 0; k < 25; k++) {
                float4 w1 = wti[k], hv = hb[k];
                ti += w1.x * hv.x + w1.y * hv.y + w1.z * hv.z + w1.w * hv.w;
                float4 w2 = wts[k], sv = st[k];
                ss += w2.x * sv.x + w2.y * sv.y + w2.z * sv.z + w2.w * sv.w;
            }
            acc_ti = ti; acc_sts = ss;
        } else if (tid >= 256) {
            int b = (tid >= 288) ? 1 : 0;
            int lane = tid & 31;
            const float* hb = sh + b * Hc;
            const float* st = sstate + b * Hc;
            float s1 = 0.f, s2 = 0.f, s3 = 0.f, s4 = 0.f;
#pragma unroll
            for (int it = 0; it < 3; it++) {
                int k = lane + it * 32;
                float hv = hb[k];
                s1 += hv; s2 += hv * hv; s3 += hv * sWlgr[k]; s4 += st[k] * sWls[k];
            }
            if (lane < 4) {
                int k = lane + 96;
                float hv = hb[k];
                s1 += hv; s2 += hv * hv; s3 += hv * sWlgr[k]; s4 += st[k] * sWls[k];
            }
#pragma unroll
            for (int o = 16; o; o >>= 1) {
                s1 += __shfl_xor_sync(0xffffffffu, s1, o);
                s2 += __shfl_xor_sync(0xffffffffu, s2, o);
                s3 += __shfl_xor_sync(0xffffffffu, s3, o);
                s4 += __shfl_xor_sync(0xffffffffu, s4, o);
            }
            if (lane == 0) {
                float norm  = sqrtf(s2);
                float denom = fmaxf(norm, 1e-12f);
                float att   = (s1 / denom) * 0.001f;     // qn = 0.1, /H = /100
                int   len   = b ? len1 : len0;
                float z     = (t < len) ? fmaxf(att, 0.f) : 0.f;
                float gate  = 1.f / (1.f + expf(-(s3 + s4 + blgr)));
                ssc[b]     = z;
                ssc[2 + b] = gate;
            }
        }
        __syncthreads();

        // ---- Stage D: state update -----------------------------------------
        if (tid < 200) {
            int b = tid & 1, i = tid >> 1;
            float z    = ssc[b];
            float gate = ssc[2 + b];
            float ns   = tanhf(acc_ti + gate * acc_sts + sbts[i]);
            float sold = sstate[b * Hc + i];
            sstate[b * Hc + i] = (1.f - z) * sold + z * ns;
        }
        // no sync needed: next reads of sstate happen after >=2 barriers
    }
    __syncthreads();

    // ---- Output head: out = state @ W_out^T + b_out ------------------------
    if (tid < 2 * NCc) {
        int b = tid / NCc, c = tid % NCc;
        float acc = b_out[c];
        const float* st = sstate + b * Hc;
        for (int k = 0; k < Hc; k++) acc += st[k] * W_out[c * Hc + k];
        out[(gb0 + b) * NCc + c] = acc;
    }
}

// ---------------------------------------------------------------------------
extern "C" void kernel_launch(void* const* d_in, const int* in_sizes, int n_in,
                              void* d_out, int out_size) {
    const int*   txt   = (const int*)d_in[0];
    const int*   lens  = (const int*)d_in[1];
    const float* emb   = (const float*)d_in[2];
    const float* W_ih  = (const float*)d_in[3];
    const float* W_hh  = (const float*)d_in[4];
    const float* b_ih  = (const float*)d_in[5];
    const float* b_hh  = (const float*)d_in[6];
    const float* W_lgr = (const float*)d_in[7];
    const float* b_lgr = (const float*)d_in[8];
    const float* W_ts  = (const float*)d_in[9];
    const float* b_ts  = (const float*)d_in[10];
    const float* W_ti  = (const float*)d_in[11];
    const float* b_ti  = (const float*)d_in[12];
    const float* W_out = (const float*)d_in[13];
    const float* b_out = (const float*)d_in[14];
    float*       out   = (float*)d_out;

    (void)in_sizes; (void)n_in; (void)out_size;

    // Kernel 1: per-row norm scales (one warp per row)
    row_norm_kernel<<<(Bc * Tc) / 8, 256>>>(txt, emb);

    // Kernel 2: xp GEMM via 3xTF32 mma.  grid.x = n (5), grid.y = m (1024)
    dim3 g2(5, (Bc * Tc) / 128);
    gemm_xp_tf32_kernel<<<g2, 256>>>(txt, emb, W_ih, b_ih);

    // Kernel 3: fused scans
    static const size_t smem_bytes = SCAN_SMEM_FLOATS * sizeof(float);
    cudaFuncSetAttribute(scan_kernel,
                         cudaFuncAttributeMaxDynamicSharedMemorySize,
                         (int)smem_bytes);
    scan_kernel<<<Bc / 2, SCAN_THREADS, smem_bytes>>>(
        W_hh, b_hh, W_lgr, b_lgr, W_ts, b_ts, W_ti, b_ti, W_out, b_out,
        lens, out);
}